// round 4
// baseline (speedup 1.0000x reference)
#include <cuda_runtime.h>

// EEG_SimpleLSM: 3-layer LIF winner-take-all liquid state machine.
// x: [256, 32, 4000] f32, W1: [64,32], W2: [128,64]. Output: exp(pre_v2@T-1) [256,128].
//
// ROUND 4: warp-specialized, 2 warps per sample. Round 3 showed each warp is
// issue-bound (~85% issue on its SMSP, ~175 instr/step) with 336 SMSPs idle.
// Split each sample's per-step work across two warps:
//   Warp A: L0 charge/reset + key store (argmax is NOT on the reset path),
//           plus all of L2 (2 batches behind, via tokens).
//   Warp B: L0 argmax from stored keys + all of L1; emits packed (s1,idx1).
// Handoff in batches of 8 steps through double-buffered smem, one
// __syncthreads per batch. CTA = 128 thr = 2 samples x 2 warps, grid 128:
// one CTA per SM, one warp per SMSP -> zero scheduler contention, 512 active
// SMSPs instead of 256.
//
// Numerics: identical operations in identical order per value (Markstein
// correctly-rounded constant division; fma gathers with s in {0,1} exact;
// REDUX max on monotone keys + REDUX min first-index tie-break). Pure
// reordering across lanes/warps only -> bit-identical to round 3.

#define NB    256
#define NCH   32
#define NT    4000
#define BATCH 8
#define NBLK  (NT / BATCH)   // 500

__device__ __align__(16) float g_W1T[32 * 64];   // W1T[c][j] = W1[j][c]
__device__ __align__(16) float g_W2T[64 * 128];  // W2T[c][j] = W2[j][c]

__global__ void prep_kernel(const float* __restrict__ W1, const float* __restrict__ W2) {
    int tid = blockIdx.x * blockDim.x + threadIdx.x;
    int nthr = blockDim.x * gridDim.x;
    for (int i = tid; i < 64 * 32; i += nthr) {
        int r = i >> 5, c = i & 31;
        g_W1T[c * 64 + r] = W1[i];
    }
    for (int i = tid; i < 128 * 64; i += nthr) {
        int r = i >> 6, c = i & 63;
        g_W2T[c * 128 + r] = W2[i];
    }
}

// Correctly-rounded division by constant c (rc = RN(1/c)), Markstein sequence.
__device__ __forceinline__ float divc(float v, float c, float rc) {
    float q = v * rc;
    float r = __fmaf_rn(-c, q, v);
    return __fmaf_rn(r, rc, q);
}

// Monotone key: strictly order-preserving float -> unsigned mapping.
__device__ __forceinline__ unsigned fkey(float v) {
    unsigned b = __float_as_uint(v);
    return b ^ ((unsigned)((int)b >> 31) | 0x80000000u);
}

// key(1.5f): 0x3FC00000 -> 0xBFC00000 ; key(1.2f): 0x3F99999A -> 0xBF99999A
#define KEY_VTH0 0xBFC00000u
#define KEY_VTH1 0xBF99999Au

__global__ void __launch_bounds__(128)
lsm_kernel(const float* __restrict__ x, float* __restrict__ out) {
    // [sample][slot][step][chan] keys; [sample][slot][step] tokens
    __shared__ unsigned s_key[2][2][BATCH][32];
    __shared__ unsigned s_tok[2][2][BATCH];

    const int tid  = threadIdx.x;
    const int lane = tid & 31;
    const int warp = tid >> 5;
    const int samp = warp >> 1;
    const int role = warp & 1;          // 0 = A (L0+L2), 1 = B (argmax+L1)
    const int b    = (blockIdx.x << 1) + samp;

    const float RCT = 1.0f / 80000.0f;

    // Role A state
    float  v0 = 0.0f;
    float4 v2 = make_float4(0.f, 0.f, 0.f, 0.f);
    float4 pc = make_float4(0.f, 0.f, 0.f, 0.f);
    float4 c0, c1;
    // Role B state
    float v1a = 0.0f, v1b = 0.0f;

    const float4* xp  = reinterpret_cast<const float4*>(x + (size_t)b * (NCH * NT) + lane * NT);
    const float2* w1p = reinterpret_cast<const float2*>(g_W1T);
    const float4* w2p = reinterpret_cast<const float4*>(g_W2T);

    if (role == 0) { c0 = __ldg(xp); c1 = __ldg(xp + 1); }

    for (int i = 0; i < NBLK + 2; ++i) {
        if (role == 0) {
            // ---- A: L0 batch i ----
            if (i < NBLK) {
                int nb = (i + 1 < NBLK) ? (i + 1) * 2 : 0;
                float4 n0 = __ldg(xp + nb);
                float4 n1 = __ldg(xp + nb + 1);
                float xs[8] = {c0.x, c0.y, c0.z, c0.w, c1.x, c1.y, c1.z, c1.w};
                unsigned* kb = &s_key[samp][i & 1][0][0];
#pragma unroll
                for (int j = 0; j < BATCH; ++j) {
                    float d0 = divc(v0, 3.0f, 1.0f / 3.0f);
                    float ch = (v0 + xs[j]) - d0;
                    kb[j * 32 + lane] = fkey(ch);
                    v0 = (ch >= 1.5f) ? 0.0f : ch;   // reset independent of argmax
                }
                c0 = n0; c1 = n1;
            }
            // ---- A: L2 batch i-2 (tokens in slot (i-2)&1 == i&1) ----
            if (i >= 2) {
                const unsigned* tb = &s_tok[samp][i & 1][0];
#pragma unroll
                for (int j = 0; j < BATCH; ++j) {
                    unsigned tok  = tb[j];
                    unsigned idx1 = tok & 0x7FFFFFFFu;
                    float s1 = (tok & 0x80000000u) ? 1.0f : 0.0f;
                    float4 w2 = __ldg(w2p + (idx1 << 5) + lane);  // W2T[idx1][4l..4l+3]
                    float dx = divc(v2.x, 80000.0f, RCT);
                    float dy = divc(v2.y, 80000.0f, RCT);
                    float dz = divc(v2.z, 80000.0f, RCT);
                    float dw = divc(v2.w, 80000.0f, RCT);
                    pc.x = __fmaf_rn(w2.x, s1, v2.x) - dx;
                    pc.y = __fmaf_rn(w2.y, s1, v2.y) - dy;
                    pc.z = __fmaf_rn(w2.z, s1, v2.z) - dz;
                    pc.w = __fmaf_rn(w2.w, s1, v2.w) - dw;
                    v2.x = (pc.x >= 1.2f) ? 0.0f : pc.x;
                    v2.y = (pc.y >= 1.2f) ? 0.0f : pc.y;
                    v2.z = (pc.z >= 1.2f) ? 0.0f : pc.z;
                    v2.w = (pc.w >= 1.2f) ? 0.0f : pc.w;
                }
            }
        } else {
            // ---- B: L0-argmax + L1, batch i-1 ----
            if (i >= 1 && i <= NBLK) {
                const unsigned* kb = &s_key[samp][(i - 1) & 1][0][0];
                unsigned* tb = &s_tok[samp][(i - 1) & 1][0];
#pragma unroll
                for (int j = 0; j < BATCH; ++j) {
                    unsigned k0 = kb[j * 32 + lane];
                    unsigned m0 = __reduce_max_sync(0xFFFFFFFFu, k0);
                    unsigned cand0 = (k0 == m0) ? (unsigned)lane : 32u;
                    unsigned idx0 = __reduce_min_sync(0xFFFFFFFFu, cand0);
                    float s0 = (m0 >= KEY_VTH0) ? 1.0f : 0.0f;

                    float2 w1 = __ldg(w1p + (idx0 << 5) + lane);  // W1T[idx0][2l..2l+1]
                    float d1a = divc(v1a, 80000.0f, RCT);
                    float d1b = divc(v1b, 80000.0f, RCT);
                    float cha = __fmaf_rn(w1.x, s0, v1a) - d1a;   // exact: s0 in {0,1}
                    float chb = __fmaf_rn(w1.y, s0, v1b) - d1b;

                    unsigned ka = fkey(cha);
                    unsigned kbk = fkey(chb);
                    bool bw = kbk > ka;
                    unsigned lk = bw ? kbk : ka;
                    unsigned li = 2u * (unsigned)lane + (bw ? 1u : 0u);
                    unsigned m1 = __reduce_max_sync(0xFFFFFFFFu, lk);
                    unsigned cand1 = (lk == m1) ? li : 64u;
                    unsigned idx1 = __reduce_min_sync(0xFFFFFFFFu, cand1);
                    unsigned tok = idx1 | ((m1 >= KEY_VTH1) ? 0x80000000u : 0u);
                    if (lane == 0) tb[j] = tok;

                    v1a = (cha >= 1.2f) ? 0.0f : cha;
                    v1b = (chb >= 1.2f) ? 0.0f : chb;
                }
            }
        }
        __syncthreads();
    }

    if (role == 0) {
        float4 o;
        o.x = expf(pc.x);
        o.y = expf(pc.y);
        o.z = expf(pc.z);
        o.w = expf(pc.w);
        reinterpret_cast<float4*>(out + (size_t)b * 128)[lane] = o;
    }
}

extern "C" void kernel_launch(void* const* d_in, const int* in_sizes, int n_in,
                              void* d_out, int out_size) {
    const float* x  = (const float*)d_in[0];
    const float* W1 = (const float*)d_in[1];
    const float* W2 = (const float*)d_in[2];
    float* out = (float*)d_out;

    prep_kernel<<<1, 256>>>(W1, W2);
    lsm_kernel<<<NB / 2, 128>>>(x, out);
}